// round 15
// baseline (speedup 1.0000x reference)
#include <cuda_runtime.h>
#include <cuda_fp16.h>
#include <cstdint>
#include <math.h>

#define BN    16
#define KCH   10
#define H     224
#define W     224
#define TS    15
#define TT    225

#define CROW  240                  // canvas row stride (elements)
#define S_IMG (238*CROW)           // 57120 per image
#define KU    (BN*S_IMG)           // 913920
#define PS_X  931648               // X canvas plane size (covers u0max+127+14*240)
#define PSY   928320               // Y canvas plane size (covers q max 928,274)

#define TILEK 128
#define NTILE 49
#define CTAK  (NTILE*TILEK)        // 6272
#define GRIDG 148                  // 148*6272 = 928256 >= KU

#define NT    640                  // 20 warps: 5 per SMSP, balanced

#define SROW  272                  // smem row stride bytes (256B data + 16B pad)
#define MAT_BYTES (160*SROW)       // 43520
#define NSTAGE 2
#define DSMEM (NSTAGE*2*MAT_BYTES) // 174080

#define CN     160
#define PELEM2 (150*CN)            // 24000 per CTA
#define E4     (PELEM2/4)          // 6000

// ---------------- scratch ----------------
__device__ __align__(256) __half g_Xc[(size_t)KCH*PS_X];        // 18.6 MB
__device__ __align__(256) __half g_Yc[(size_t)4*KCH*PSY];       // 74.3 MB (4 parity canvases)
__device__ float g_part[(size_t)GRIDG*PELEM2];                  // 14.2 MB
__device__ float g_mid[(size_t)8*PELEM2];
__device__ float g_p[PELEM2];
__device__ float g_min[1];

// ---------------- PTX helpers (plain sm_80-era features only) ----------------
__device__ __forceinline__ uint32_t smem_u32(const void* p) {
    uint32_t a;
    asm("{ .reg .u64 t; cvta.to.shared.u64 t, %1; cvt.u32.u64 %0, t; }" : "=r"(a) : "l"(p));
    return a;
}
#define CP_COMMIT() asm volatile("cp.async.commit_group;" ::: "memory")
#define CP_WAIT1()  asm volatile("cp.async.wait_group 1;" ::: "memory")

__device__ __forceinline__ void ldsm4(uint32_t& r0, uint32_t& r1, uint32_t& r2, uint32_t& r3,
                                      uint32_t addr) {
    asm volatile("ldmatrix.sync.aligned.m8n8.x4.shared.b16 {%0,%1,%2,%3}, [%4];"
                 : "=r"(r0), "=r"(r1), "=r"(r2), "=r"(r3) : "r"(addr));
}
__device__ __forceinline__ void ldsm2(uint32_t& r0, uint32_t& r1, uint32_t addr) {
    asm volatile("ldmatrix.sync.aligned.m8n8.x2.shared.b16 {%0,%1}, [%2];"
                 : "=r"(r0), "=r"(r1) : "r"(addr));
}
__device__ __forceinline__ void mma16816(float* d,
        uint32_t a0, uint32_t a1, uint32_t a2, uint32_t a3,
        uint32_t b0, uint32_t b1) {
    asm volatile("mma.sync.aligned.m16n8k16.row.col.f32.f16.f16.f32 "
                 "{%0,%1,%2,%3}, {%4,%5,%6,%7}, {%8,%9}, {%0,%1,%2,%3};"
                 : "+f"(d[0]), "+f"(d[1]), "+f"(d[2]), "+f"(d[3])
                 : "r"(a0), "r"(a1), "r"(a2), "r"(a3), "r"(b0), "r"(b1));
}

// ---------------- pack x_out -> zero-padded fp16 canvas ----------------
__global__ void pack_x_f16(const float* __restrict__ x) {
    int p = blockIdx.x * blockDim.x + threadIdx.x;
    int n = blockIdx.y;
    if (p >= PS_X) return;
    float v = 0.0f;
    if (p < KU) {
        int b  = p / S_IMG;
        int pp = p - b * S_IMG;
        int yy = pp / CROW, xx = pp - yy * CROW;
        if (yy >= 7 && yy < 231 && xx >= 7 && xx < 231)
            v = x[(((size_t)b*KCH + n)*H + (yy-7))*W + (xx-7)];
    }
    g_Xc[(size_t)n*PS_X + p] = __float2half(v);
}

// ---------------- pack x_tf_out -> 4 parity-shifted fp16 canvases ----------------
// Canvas s: C_s[q] = Y[q - 16 - s] (zero out of range); q in [0,16) stays module-zero.
__global__ void pack_y_f16(const float* __restrict__ y) {
    int p = blockIdx.x * blockDim.x + threadIdx.x;
    int o = blockIdx.y;
    if (p >= PSY) return;
    float v = 0.0f;
    if (p < KU) {
        int b  = p / S_IMG;
        int pp = p - b * S_IMG;
        int yy = pp / CROW, xx = pp - yy * CROW;
        if (yy < H && xx < W)
            v = y[(((size_t)b*KCH + o)*H + yy)*W + xx];
    }
    __half hv = __float2half(v);
#pragma unroll
    for (int s = 0; s < 4; s++) {
        int q = p + 16 + s;
        if (q < PSY) g_Yc[(size_t)(s*KCH + o)*PSY + q] = hv;
    }
}

// ---------------- trivial init: placed 3rd so gemm is the profiled 4th launch ----------------
__global__ void init_kernel() { g_min[0] = 0.0f; }

// ---------------- staging: gather A'/B' K=128 tiles into SMEM via cp.async ----------------
__device__ __forceinline__ void stage(int u0, uint32_t sA, uint32_t sB, int tid) {
#pragma unroll 4
    for (int i = tid; i < 2400; i += NT) {             // A: 150 rows x 16 x 16B
        int r = i >> 4, c = i & 15;
        int dy = r / 10, n = r - dy*10;
        const __half* src = g_Xc + (size_t)n*PS_X + (u0 + dy*CROW + c*8);
        asm volatile("cp.async.cg.shared.global [%0], [%1], 16;"
                     :: "r"(sA + r*SROW + c*16), "l"(src));
    }
#pragma unroll 8
    for (int i = tid; i < 4800; i += NT) {             // B: 150 rows x 32 x 8B
        int r = i >> 5, c = i & 31;
        int dx = r / 10, o = r - dx*10;
        int s = dx & 3;
        int q = u0 + c*4 - dx + s + 16;                // 8B aligned, always >= 4
        const __half* src = g_Yc + (size_t)(s*KCH + o)*PSY + q;
        asm volatile("cp.async.ca.shared.global [%0], [%1], 8;"
                     :: "r"(sB + r*SROW + c*8), "l"(src));
    }
}

// ---------------- per-tile warp MMA: m32 x n40, K=128 ----------------
__device__ __forceinline__ void compute_tile(uint32_t bufA, uint32_t bufB,
                                             int mBase, int nBase, int l,
                                             float acc[2][5][4]) {
    uint32_t aBase = bufA + (mBase + (l & 15))*SROW + ((l >> 4) & 1)*16;
    uint32_t bBase4 = bufB + (nBase + (l & 7) + ((l & 16) ? 8 : 0))*SROW + ((l & 8) ? 16 : 0);
    uint32_t bBase2 = bufB + (nBase + 32 + (l & 7))*SROW + ((l & 8) ? 16 : 0);
#pragma unroll
    for (int kk = 0; kk < 8; kk++) {
        uint32_t a00, a01, a02, a03, a10, a11, a12, a13;
        ldsm4(a00, a01, a02, a03, aBase + kk*32);
        ldsm4(a10, a11, a12, a13, aBase + 16*SROW + kk*32);
        uint32_t b0, b1, b2, b3, b4, b5, b6, b7, b8, b9;
        ldsm4(b0, b1, b2, b3, bBase4 + kk*32);                // n8 tiles 0,1
        ldsm4(b4, b5, b6, b7, bBase4 + 16*SROW + kk*32);      // n8 tiles 2,3
        ldsm2(b8, b9, bBase2 + kk*32);                        // n8 tile 4
        mma16816(acc[0][0], a00, a01, a02, a03, b0, b1);
        mma16816(acc[0][1], a00, a01, a02, a03, b2, b3);
        mma16816(acc[0][2], a00, a01, a02, a03, b4, b5);
        mma16816(acc[0][3], a00, a01, a02, a03, b6, b7);
        mma16816(acc[0][4], a00, a01, a02, a03, b8, b9);
        mma16816(acc[1][0], a10, a11, a12, a13, b0, b1);
        mma16816(acc[1][1], a10, a11, a12, a13, b2, b3);
        mma16816(acc[1][2], a10, a11, a12, a13, b4, b5);
        mma16816(acc[1][3], a10, a11, a12, a13, b6, b7);
        mma16816(acc[1][4], a10, a11, a12, a13, b8, b9);
    }
}

// ---------------- GEMM: C[150,150] += A'·B'^T over this CTA's K chunk ----------------
__global__ __launch_bounds__(NT, 1) void gemm_kernel() {
    extern __shared__ char smem[];
    uint32_t sb = smem_u32(smem);
    int tid = threadIdx.x;
    int w = tid >> 5, l = tid & 31;
    int mBase = (w % 5) * 32;      // 5 m-strips of 32
    int nBase = (w / 5) * 40;      // 4 n-quarters of 40

    // zero pad rows 150-159 of all 4 matrices (never touched by staging)
    for (int i = tid; i < 4*680; i += NT) {
        int mtx = i / 680, off = i - mtx*680;
        *reinterpret_cast<uint32_t*>(smem + mtx*MAT_BYTES + 150*SROW + off*4) = 0;
    }

    int u0 = blockIdx.x * CTAK;

    // prologue: stages 0 and 1
    stage(u0,         sb,                 sb + MAT_BYTES,   tid);
    CP_COMMIT();
    stage(u0 + TILEK, sb + 2*MAT_BYTES,   sb + 3*MAT_BYTES, tid);
    CP_COMMIT();

    float acc[2][5][4];
#pragma unroll
    for (int s = 0; s < 2; s++)
#pragma unroll
        for (int j = 0; j < 5; j++)
#pragma unroll
            for (int c = 0; c < 4; c++) acc[s][j][c] = 0.0f;

    for (int i = 0; i < NTILE; i++) {
        CP_WAIT1();                // group i complete; group i+1 in flight
        __syncthreads();           // tile i visible to all warps
        int cm = i & 1;
        compute_tile(sb + cm*(2*MAT_BYTES), sb + cm*(2*MAT_BYTES) + MAT_BYTES,
                     mBase, nBase, l, acc);
        __syncthreads();           // everyone done reading buf cm
        if (i + 2 < NTILE)
            stage(u0 + (i + 2)*TILEK, sb + cm*(2*MAT_BYTES),
                  sb + cm*(2*MAT_BYTES) + MAT_BYTES, tid);
        CP_COMMIT();               // uniform group count (possibly empty)
    }

    // epilogue: fragment rows mBase+16s+{l>>2, +8}; cols nBase + j*8 + 2*(l&3)
    float* dst = g_part + (size_t)blockIdx.x * PELEM2;
#pragma unroll
    for (int s = 0; s < 2; s++) {
        int r0 = mBase + 16*s + (l >> 2);
#pragma unroll
        for (int j = 0; j < 5; j++) {
            int n = nBase + j*8 + 2*(l & 3);
            if (r0 < 150) {
                dst[r0*CN + n]     = acc[s][j][0];
                dst[r0*CN + n + 1] = acc[s][j][1];
            }
            if (r0 + 8 < 150) {
                dst[(r0 + 8)*CN + n]     = acc[s][j][2];
                dst[(r0 + 8)*CN + n + 1] = acc[s][j][3];
            }
        }
    }
}

// ---------------- reduce partials (2-stage) ----------------
__global__ void reduce1_kernel() {
    int e = blockIdx.x * blockDim.x + threadIdx.x;   // float4 index
    if (e >= E4) return;
    int c0 = blockIdx.y * 19;
    int c1 = min(c0 + 19, GRIDG);
    float4 sum = make_float4(0.f, 0.f, 0.f, 0.f);
    const float4* src = reinterpret_cast<const float4*>(g_part);
    for (int c = c0; c < c1; c++) {
        float4 v = src[(size_t)c*E4 + e];
        sum.x += v.x; sum.y += v.y; sum.z += v.z; sum.w += v.w;
    }
    reinterpret_cast<float4*>(g_mid)[(size_t)blockIdx.y*E4 + e] = sum;
}
__global__ void reduce2_kernel() {
    int e = blockIdx.x * blockDim.x + threadIdx.x;
    if (e >= E4) return;
    float4 sum = make_float4(0.f, 0.f, 0.f, 0.f);
    const float4* src = reinterpret_cast<const float4*>(g_mid);
    for (int c = 0; c < 8; c++) {
        float4 v = src[(size_t)c*E4 + e];
        sum.x += v.x; sum.y += v.y; sum.z += v.z; sum.w += v.w;
    }
    reinterpret_cast<float4*>(g_p)[e] = sum;
}

// ---------------- fused min + loss epilogue (exact reference math, fp32) ----------------
__global__ void loss_kernel(float* __restrict__ out) {
    __shared__ float ssum[256];
    int t = threadIdx.x;

    // --- global min over valid 150x150 ---
    float m = 3.4e38f;
    for (int e = t; e < 22500; e += 256) {
        int r = e / 150, c = e - r*150;
        m = fminf(m, g_p[r*CN + c]);
    }
    ssum[t] = m;
    __syncthreads();
    for (int w2 = 128; w2 > 0; w2 >>= 1) {
        if (t < w2) ssum[t] = fminf(ssum[t], ssum[t + w2]);
        __syncthreads();
    }
    const float gmin = ssum[0];
    __syncthreads();

    // --- loss ---
    float part = 0.0f;
    const float EPS = 1e-16f;
    if (t < TT) {
        int dy = t / TS, dx = t - dy*TS;
        float v[KCH*KCH];
        float tot = 0.0f;
        for (int n = 0; n < KCH; n++)
            for (int o = 0; o < KCH; o++) {
                float q = g_p[(dy*10 + n)*CN + (dx*10 + o)] - gmin + EPS;
                v[n*KCH + o] = q;
                tot += q;
            }
        float inv = 1.0f / tot;
        float pi[KCH], pj[KCH];
#pragma unroll
        for (int o = 0; o < KCH; o++) { pi[o] = 0.0f; pj[o] = 0.0f; }
        for (int n = 0; n < KCH; n++)
            for (int o = 0; o < KCH; o++) {
                float q = 0.5f * (v[n*KCH + o] + v[o*KCH + n]) * inv;
                pi[o] += q;
                pj[n] += q;
            }
        for (int n = 0; n < KCH; n++)
            for (int o = 0; o < KCH; o++) {
                float q = 0.5f * (v[n*KCH + o] + v[o*KCH + n]) * inv;
                part += -q * (logf(q + EPS) - logf(pi[o] + EPS) - logf(pj[n] + EPS));
            }
    }
    ssum[t] = part;
    __syncthreads();
    for (int w2 = 128; w2 > 0; w2 >>= 1) {
        if (t < w2) ssum[t] += ssum[t + w2];
        __syncthreads();
    }
    if (t == 0) out[0] = ssum[0] / (float)TT;
}

// ---------------- launch ----------------
extern "C" void kernel_launch(void* const* d_in, const int* in_sizes, int n_in,
                              void* d_out, int out_size) {
    const float* x = (const float*)d_in[0];   // x_out     (16,10,224,224) f32
    const float* y = (const float*)d_in[1];   // x_tf_out  (16,10,224,224) f32
    float* out = (float*)d_out;

    cudaFuncSetAttribute(gemm_kernel,
                         cudaFuncAttributeMaxDynamicSharedMemorySize, DSMEM);

    pack_x_f16<<<dim3((PS_X + 255)/256, KCH), 256>>>(x);
    pack_y_f16<<<dim3((PSY + 255)/256, KCH), 256>>>(y);
    init_kernel<<<1, 1>>>();                       // launch #3 -> gemm profiled as #4
    gemm_kernel<<<GRIDG, NT, DSMEM>>>();
    reduce1_kernel<<<dim3((E4 + 255)/256, 8), 256>>>();
    reduce2_kernel<<<(E4 + 255)/256, 256>>>();
    loss_kernel<<<1, 256>>>(out);
}